// round 1
// baseline (speedup 1.0000x reference)
#include <cuda_runtime.h>

#define FH   45
#define FW   80
#define CC   64
#define BB   16
#define NN   2784
#define JOUT 75          // 2 cls + 73 reg outputs
#define JP   80          // padded to 80 for float4 + alignment
#define ODIM 77

// Scratch (static __device__ — no allocations allowed)
__device__ float  g_WW[FH * CC * JP];        // folded weights [h][ci][j]
__device__ float  g_Bh[FH * JP];             // conv-bias contribution [h][j]
__device__ float4 g_P[BB * FH * FW * (JP/4)];// P[b][h][w][j/4], 18.4 MB

// ---------------------------------------------------------------------------
// k1: fold conv into head weights.
// WW[ci,h,j] = sum_o conv_w[o,ci] * Wcat[o,h,j];  Bh[h,j] = sum_o conv_b[o]*Wcat[o,h,j]
// Wcat[o,h,j]: j<2 -> cls_w[(o*FH+h)*2+j]; 2<=j<75 -> reg_w[(o*FH+h)*73+(j-2)]
// ---------------------------------------------------------------------------
__global__ void k_prep(const float* __restrict__ conv_w, const float* __restrict__ conv_b,
                       const float* __restrict__ cls_w,  const float* __restrict__ reg_w) {
    int h  = blockIdx.x;
    int j  = threadIdx.x;   // 0..79
    int ty = threadIdx.y;   // 0..7
    __shared__ float sW[CC][JP];
    for (int o = ty; o < CC; o += 8) {
        float v = 0.f;
        if (j < 2)          v = cls_w[(o * FH + h) * 2 + j];
        else if (j < JOUT)  v = reg_w[(o * FH + h) * 73 + (j - 2)];
        sW[o][j] = v;
    }
    __syncthreads();
    for (int ci = ty; ci < CC; ci += 8) {
        float acc = 0.f;
#pragma unroll 16
        for (int o = 0; o < CC; o++) acc += conv_w[o * CC + ci] * sW[o][j];
        g_WW[(h * CC + ci) * JP + j] = acc;
    }
    if (ty == 0) {
        float acc = 0.f;
#pragma unroll 16
        for (int o = 0; o < CC; o++) acc += conv_b[o] * sW[o][j];
        g_Bh[h * JP + j] = acc;
    }
}

// ---------------------------------------------------------------------------
// k2: P[b,h,w,j] = sum_ci x[b,ci,h,w] * WW[ci,h,j] + Bh[h,j]
// One block per (h,b): 64x80x80 GEMM, 5x5 register tiles, smem-staged operands.
// ---------------------------------------------------------------------------
__global__ void k_pcompute(const float* __restrict__ x) {
    int h = blockIdx.x, b = blockIdx.y;
    __shared__ float sx[CC][FW];   // x[b][ci][h][w]
    __shared__ float sw[CC][JP];   // WW[h][ci][j]
    int tid = threadIdx.y * 16 + threadIdx.x;

    const float* xb  = x + ((b * CC) * FH + h) * FW;
    const float* wwh = g_WW + h * CC * JP;
    for (int i = tid; i < CC * FW; i += 256) {
        int ci = i / FW, w = i - ci * FW;
        sx[ci][w] = xb[ci * FH * FW + w];
        sw[ci][w] = wwh[i];
    }
    __syncthreads();

    int j0 = threadIdx.x * 5;   // 16*5 = 80 j
    int w0 = threadIdx.y * 5;   // 16*5 = 80 w
    float acc[5][5];
#pragma unroll
    for (int v = 0; v < 5; v++)
#pragma unroll
        for (int u = 0; u < 5; u++) acc[v][u] = 0.f;

#pragma unroll 4
    for (int ci = 0; ci < CC; ci++) {
        float wv[5], xv[5];
#pragma unroll
        for (int u = 0; u < 5; u++) wv[u] = sw[ci][j0 + u];
#pragma unroll
        for (int v = 0; v < 5; v++) xv[v] = sx[ci][w0 + v];
#pragma unroll
        for (int v = 0; v < 5; v++)
#pragma unroll
            for (int u = 0; u < 5; u++) acc[v][u] += xv[v] * wv[u];
    }

    float bh[5];
#pragma unroll
    for (int u = 0; u < 5; u++) bh[u] = g_Bh[h * JP + j0 + u];

    float* Pp = (float*)g_P + (size_t)((b * FH + h) * FW) * JP;
#pragma unroll
    for (int v = 0; v < 5; v++)
#pragma unroll
        for (int u = 0; u < 5; u++)
            Pp[(w0 + v) * JP + j0 + u] = acc[v][u] + bh[u];
}

// ---------------------------------------------------------------------------
// k3: gather-reduce over h + epilogue.
// block = (20,16): 16 anchors, 20 float4 lanes (j). grid = (NN/16, B).
// out[b,n,0:2]=cls; out[2:4]=anchors[2:4]; out[4:77]=anchors[4:]+reg
// ---------------------------------------------------------------------------
__global__ void k_gather(const float* __restrict__ cls_b, const float* __restrict__ reg_b,
                         const float* __restrict__ anchors,
                         const int* __restrict__ cut_xs,
                         const unsigned char* __restrict__ invalid,
                         float* __restrict__ out) {
    int n0 = blockIdx.x * 16;
    int b  = blockIdx.y;
    __shared__ int   offs[16][FH];
    __shared__ float scl[16][FH];

    int tid = threadIdx.y * 20 + threadIdx.x;
    for (int t = tid; t < 16 * FH; t += 320) {
        int a = t / FH, h = t - a * FH;
        int n = n0 + a;
        int xv = cut_xs[n * FH + h];
        xv = min(max(xv, 0), FW - 1);
        offs[a][h] = (h * FW + xv) * (JP / 4);
        scl[a][h]  = invalid[n * FH + h] ? 0.f : 1.f;
    }
    __syncthreads();

    int tx = threadIdx.x;      // 0..19, j = 4*tx .. 4*tx+3
    int a  = threadIdx.y;      // 0..15
    int n  = n0 + a;
    const float4* Pb = g_P + (size_t)b * FH * FW * (JP / 4);

    int jb = tx * 4;
    float4 acc;
    acc.x = (jb + 0 < 2) ? cls_b[jb + 0] : ((jb + 0 < JOUT) ? reg_b[jb - 2] : 0.f);
    acc.y = (jb + 1 < 2) ? cls_b[jb + 1] : ((jb + 1 < JOUT) ? reg_b[jb - 1] : 0.f);
    acc.z = (jb + 2 < JOUT) ? ((jb + 2 < 2) ? cls_b[jb + 2] : reg_b[jb + 0]) : 0.f;
    acc.w = (jb + 3 < JOUT) ? reg_b[jb + 1] : 0.f;   // jb+3 >= 3 always -> reg side

#pragma unroll 5
    for (int h = 0; h < FH; h++) {
        float  s = scl[a][h];
        float4 p = Pb[offs[a][h] + tx];
        acc.x += s * p.x;
        acc.y += s * p.y;
        acc.z += s * p.z;
        acc.w += s * p.w;
    }

    int obase = (b * NN + n) * ODIM;
    const float* an = anchors + n * ODIM;
    float av[4] = {acc.x, acc.y, acc.z, acc.w};
#pragma unroll
    for (int u = 0; u < 4; u++) {
        int j = jb + u;
        if (j < 2)          out[obase + j]     = av[u];
        else if (j < JOUT)  out[obase + j + 2] = an[j + 2] + av[u];
    }
    if (tx == 19) {
        out[obase + 2] = an[2];
        out[obase + 3] = an[3];
    }
}

// ---------------------------------------------------------------------------
extern "C" void kernel_launch(void* const* d_in, const int* in_sizes, int n_in,
                              void* d_out, int out_size) {
    const float* x       = (const float*)d_in[0];
    const float* conv_w  = (const float*)d_in[1];
    const float* conv_b  = (const float*)d_in[2];
    const float* cls_w   = (const float*)d_in[3];
    const float* cls_b   = (const float*)d_in[4];
    const float* reg_w   = (const float*)d_in[5];
    const float* reg_b   = (const float*)d_in[6];
    const float* anchors = (const float*)d_in[7];
    const int*   cut_xs  = (const int*)d_in[8];
    const unsigned char* invalid = (const unsigned char*)d_in[9];
    float* out = (float*)d_out;

    k_prep    <<<dim3(FH),        dim3(JP, 8)>>>(conv_w, conv_b, cls_w, reg_w);
    k_pcompute<<<dim3(FH, BB),    dim3(16, 16)>>>(x);
    k_gather  <<<dim3(NN/16, BB), dim3(20, 16)>>>(cls_b, reg_b, anchors, cut_xs, invalid, out);
}

// round 2
// speedup vs baseline: 1.0057x; 1.0057x over previous
#include <cuda_runtime.h>

#define FH   45
#define FW   80
#define CC   64
#define BB   16
#define NN   2784
#define JOUT 75          // 2 cls + 73 reg outputs
#define JP   80          // padded for alignment
#define ODIM 77

// Scratch (static __device__ — no allocations allowed)
__device__ float  g_WW[FH * CC * JP];        // folded weights [h][ci][j]
__device__ float  g_Bh[FH * JP];             // conv-bias contribution [h][j]
__device__ float4 g_P[BB * FH * FW * (JP/4)];// P[b][h][w][j/4], 18.4 MB

// ---------------------------------------------------------------------------
// k1: fold conv into head weights (smem-staged conv_w, 8-ci register tile).
// WW[ci,h,j] = sum_o conv_w[o,ci] * Wcat[o,h,j];  Bh[h,j] = sum_o conv_b[o]*Wcat[o,h,j]
// ---------------------------------------------------------------------------
__global__ void k_prep(const float* __restrict__ conv_w, const float* __restrict__ conv_b,
                       const float* __restrict__ cls_w,  const float* __restrict__ reg_w) {
    int h  = blockIdx.x;
    int j  = threadIdx.x;   // 0..79
    int ty = threadIdx.y;   // 0..7
    __shared__ float sW[CC][JP];     // Wcat[o][j] for this h
    __shared__ float scw[CC][CC];    // conv_w[o][ci]

    int tid = ty * JP + j;           // 0..639
    for (int i = tid; i < CC * CC; i += 640) scw[i >> 6][i & 63] = conv_w[i];
    for (int o = ty; o < CC; o += 8) {
        float v = 0.f;
        if (j < 2)          v = cls_w[(o * FH + h) * 2 + j];
        else if (j < JOUT)  v = reg_w[(o * FH + h) * 73 + (j - 2)];
        sW[o][j] = v;
    }
    __syncthreads();

    float acc[8];
#pragma unroll
    for (int k = 0; k < 8; k++) acc[k] = 0.f;
    float accb = 0.f;

#pragma unroll 8
    for (int o = 0; o < CC; o++) {
        float wv = sW[o][j];
#pragma unroll
        for (int k = 0; k < 8; k++) acc[k] += scw[o][ty + 8 * k] * wv;
        if (ty == 0) accb += conv_b[o] * wv;
    }

#pragma unroll
    for (int k = 0; k < 8; k++) {
        int ci = ty + 8 * k;
        g_WW[(h * CC + ci) * JP + j] = acc[k];
    }
    if (ty == 0) g_Bh[h * JP + j] = accb;
}

// ---------------------------------------------------------------------------
// k2: P[b,h,w,j] = sum_ci x[b,ci,h,w] * WW[ci,h,j] + Bh[h,j]
// One block per (h,b): 64x80x80 GEMM, 5x5 register tiles, smem-staged operands.
// ---------------------------------------------------------------------------
__global__ void k_pcompute(const float* __restrict__ x) {
    int h = blockIdx.x, b = blockIdx.y;
    __shared__ float sx[CC][FW];   // x[b][ci][h][w]
    __shared__ float sw[CC][JP];   // WW[h][ci][j]
    int tid = threadIdx.y * 16 + threadIdx.x;

    const float* xb  = x + ((b * CC) * FH + h) * FW;
    const float* wwh = g_WW + h * CC * JP;
    for (int i = tid; i < CC * FW; i += 256) {
        int ci = i / FW, w = i - ci * FW;
        sx[ci][w] = xb[ci * FH * FW + w];
        sw[ci][w] = wwh[i];
    }
    __syncthreads();

    int j0 = threadIdx.x * 5;   // 16*5 = 80 j
    int w0 = threadIdx.y * 5;   // 16*5 = 80 w
    float acc[5][5];
#pragma unroll
    for (int v = 0; v < 5; v++)
#pragma unroll
        for (int u = 0; u < 5; u++) acc[v][u] = 0.f;

#pragma unroll 4
    for (int ci = 0; ci < CC; ci++) {
        float wv[5], xv[5];
#pragma unroll
        for (int u = 0; u < 5; u++) wv[u] = sw[ci][j0 + u];
#pragma unroll
        for (int v = 0; v < 5; v++) xv[v] = sx[ci][w0 + v];
#pragma unroll
        for (int v = 0; v < 5; v++)
#pragma unroll
            for (int u = 0; u < 5; u++) acc[v][u] += xv[v] * wv[u];
    }

    float bh[5];
#pragma unroll
    for (int u = 0; u < 5; u++) bh[u] = g_Bh[h * JP + j0 + u];

    float* Pp = (float*)g_P + (size_t)((b * FH + h) * FW) * JP;
#pragma unroll
    for (int v = 0; v < 5; v++)
#pragma unroll
        for (int u = 0; u < 5; u++)
            Pp[(w0 + v) * JP + j0 + u] = acc[v][u] + bh[u];
}

// ---------------------------------------------------------------------------
// k3: gather-reduce over VALID h only + epilogue.
// block = (19,16): 16 anchors, 19 float4 lanes (j=0..75). grid = (NN/16, B).
// ---------------------------------------------------------------------------
__global__ void k_gather(const float* __restrict__ cls_b, const float* __restrict__ reg_b,
                         const float* __restrict__ anchors,
                         const int* __restrict__ cut_xs,
                         const unsigned char* __restrict__ invalid,
                         float* __restrict__ out) {
    int n0 = blockIdx.x * 16;
    int b  = blockIdx.y;
    __shared__ int raw[16][FH];    // offset or -1 if invalid
    __shared__ int offs[16][FH];   // compacted valid offsets
    __shared__ int cnt[16];

    int tx  = threadIdx.x;      // 0..18
    int a   = threadIdx.y;      // 0..15
    int tid = a * 19 + tx;
    for (int t = tid; t < 16 * FH; t += 304) {
        int aa = t / FH, h = t - aa * FH;
        int n = n0 + aa;
        int xv = cut_xs[n * FH + h];
        xv = min(max(xv, 0), FW - 1);
        raw[aa][h] = invalid[n * FH + h] ? -1 : (h * FW + xv) * (JP / 4);
    }
    __syncthreads();
    if (tx == 0) {
        int c = 0;
#pragma unroll 9
        for (int h = 0; h < FH; h++) {
            int v = raw[a][h];
            if (v >= 0) offs[a][c++] = v;
        }
        cnt[a] = c;
    }
    __syncthreads();

    int n = n0 + a;
    const float4* Pb = g_P + (size_t)b * FH * FW * (JP / 4);

    int jb = tx * 4;
    float av[4];
#pragma unroll
    for (int u = 0; u < 4; u++) {
        int j = jb + u;
        av[u] = (j < 2) ? cls_b[j] : ((j < JOUT) ? reg_b[j - 2] : 0.f);
    }

    int c = cnt[a];
    int i = 0;
    for (; i + 5 <= c; i += 5) {
        float4 p0 = Pb[offs[a][i + 0] + tx];
        float4 p1 = Pb[offs[a][i + 1] + tx];
        float4 p2 = Pb[offs[a][i + 2] + tx];
        float4 p3 = Pb[offs[a][i + 3] + tx];
        float4 p4 = Pb[offs[a][i + 4] + tx];
        av[0] += p0.x + p1.x + p2.x + p3.x + p4.x;
        av[1] += p0.y + p1.y + p2.y + p3.y + p4.y;
        av[2] += p0.z + p1.z + p2.z + p3.z + p4.z;
        av[3] += p0.w + p1.w + p2.w + p3.w + p4.w;
    }
    for (; i < c; i++) {
        float4 p = Pb[offs[a][i] + tx];
        av[0] += p.x; av[1] += p.y; av[2] += p.z; av[3] += p.w;
    }

    int obase = (b * NN + n) * ODIM;
    const float* an = anchors + n * ODIM;
#pragma unroll
    for (int u = 0; u < 4; u++) {
        int j = jb + u;
        if (j < 2)          out[obase + j]     = av[u];
        else if (j < JOUT)  out[obase + j + 2] = an[j + 2] + av[u];
    }
    if (tx == 0) {
        out[obase + 2] = an[2];
        out[obase + 3] = an[3];
    }
}

// ---------------------------------------------------------------------------
extern "C" void kernel_launch(void* const* d_in, const int* in_sizes, int n_in,
                              void* d_out, int out_size) {
    const float* x       = (const float*)d_in[0];
    const float* conv_w  = (const float*)d_in[1];
    const float* conv_b  = (const float*)d_in[2];
    const float* cls_w   = (const float*)d_in[3];
    const float* cls_b   = (const float*)d_in[4];
    const float* reg_w   = (const float*)d_in[5];
    const float* reg_b   = (const float*)d_in[6];
    const float* anchors = (const float*)d_in[7];
    const int*   cut_xs  = (const int*)d_in[8];
    const unsigned char* invalid = (const unsigned char*)d_in[9];
    float* out = (float*)d_out;

    k_prep    <<<dim3(FH),        dim3(JP, 8)>>>(conv_w, conv_b, cls_w, reg_w);
    k_pcompute<<<dim3(FH, BB),    dim3(16, 16)>>>(x);
    k_gather  <<<dim3(NN/16, BB), dim3(19, 16)>>>(cls_b, reg_b, anchors, cut_xs, invalid, out);
}